// round 9
// baseline (speedup 1.0000x reference)
#include <cuda_runtime.h>
#include <cuda_bf16.h>
#include <cstdint>

#define NN   32
#define CC   256
#define TT   128
#define VV   25
#define KK   3
#define MIDC 64
#define KM   192
#define OUTC 256
#define TV   3200
#define MPAD 256    // padded M for pre-GEMM weights

// ---------------- scratch (device globals; no allocation) ----------------
__device__ __align__(256) float g_tmp[NN * CC * VV];
__device__ __align__(256) float g_x1[NN * KK * MIDC * VV];
__device__ __align__(256) float g_x2[NN * KK * MIDC * VV];
__device__ __align__(256) float g_gs[NN * KK * VV * VV];
__device__ __align__(256) float g_prex[NN * KM * TV];
__device__ __align__(256) __nv_bfloat16 g_x_hi[(size_t)NN * CC * TV];
__device__ __align__(256) __nv_bfloat16 g_x_lo[(size_t)NN * CC * TV];
__device__ __align__(256) __nv_bfloat16 g_y_hi[(size_t)NN * KM * TV];
__device__ __align__(256) __nv_bfloat16 g_y_lo[(size_t)NN * KM * TV];
__device__ __align__(256) __nv_bfloat16 g_wpre_hi[MPAD * CC];   // rows >= KM are zero
__device__ __align__(256) __nv_bfloat16 g_wpre_lo[MPAD * CC];
__device__ __align__(256) __nv_bfloat16 g_wpost_hi[OUTC * KM];
__device__ __align__(256) __nv_bfloat16 g_wpost_lo[OUTC * KM];

// ---------------- helpers ----------------
__device__ __forceinline__ uint32_t smem_u32(const void* p) {
    uint32_t a;
    asm("{ .reg .u64 t; cvta.to.shared.u64 t, %1; cvt.u32.u64 %0, t; }" : "=r"(a) : "l"(p));
    return a;
}
__device__ __forceinline__ void ldsm4(uint32_t* r, uint32_t addr) {
    asm volatile("ldmatrix.sync.aligned.m8n8.x4.shared.b16 {%0,%1,%2,%3}, [%4];"
                 : "=r"(r[0]), "=r"(r[1]), "=r"(r[2]), "=r"(r[3]) : "r"(addr));
}
__device__ __forceinline__ void ldsm4t(uint32_t* r, uint32_t addr) {
    asm volatile("ldmatrix.sync.aligned.m8n8.x4.trans.shared.b16 {%0,%1,%2,%3}, [%4];"
                 : "=r"(r[0]), "=r"(r[1]), "=r"(r[2]), "=r"(r[3]) : "r"(addr));
}
__device__ __forceinline__ void mma_bf16(float* d, const uint32_t* a, const uint32_t* b) {
    asm volatile(
        "mma.sync.aligned.m16n8k16.row.col.f32.bf16.bf16.f32 "
        "{%0,%1,%2,%3}, {%4,%5,%6,%7}, {%8,%9}, {%0,%1,%2,%3};"
        : "+f"(d[0]), "+f"(d[1]), "+f"(d[2]), "+f"(d[3])
        : "r"(a[0]), "r"(a[1]), "r"(a[2]), "r"(a[3]), "r"(b[0]), "r"(b[1]));
}
__device__ __forceinline__ uint32_t pack_bf(__nv_bfloat16 a, __nv_bfloat16 b) {
    return ((uint32_t)__bfloat16_as_ushort(b) << 16) | (uint32_t)__bfloat16_as_ushort(a);
}
__device__ __forceinline__ void split2pk(float x, float y, uint32_t& hi, uint32_t& lo) {
    __nv_bfloat16 hx = __float2bfloat16(x);
    __nv_bfloat16 hy = __float2bfloat16(y);
    hi = pack_bf(hx, hy);
    lo = pack_bf(__float2bfloat16(x - __bfloat162float(hx)),
                 __float2bfloat16(y - __bfloat162float(hy)));
}
__device__ __forceinline__ void split1(float v, __nv_bfloat16& h, __nv_bfloat16& l) {
    h = __float2bfloat16(v);
    l = __float2bfloat16(v - __bfloat162float(h));
}

// ---------------- kernel 1: mean over T + x bf16 split ----------------
__global__ void mean_split_kernel(const float* __restrict__ x) {
    int nc   = blockIdx.x;
    int tid  = threadIdx.x;
    int lane = tid & 31;
    int warp = tid >> 5;
    const float* base = x + (size_t)nc * (TT * VV);

    const float2* b2 = (const float2*)base;
    uint32_t* xh = (uint32_t*)(g_x_hi + (size_t)nc * (TT * VV));
    uint32_t* xl = (uint32_t*)(g_x_lo + (size_t)nc * (TT * VV));
    for (int i = tid; i < (TT * VV) / 2; i += 128) {
        float2 v = b2[i];
        uint32_t h, l;
        split2pk(v.x, v.y, h, l);
        xh[i] = h;
        xl[i] = l;
    }

    __shared__ float red[4][VV];
    if (lane < VV) {
        float s = 0.f;
        for (int t = warp; t < TT; t += 4)
            s += base[t * VV + lane];
        red[warp][lane] = s;
    }
    __syncthreads();
    if (warp == 0 && lane < VV) {
        float tot = red[0][lane] + red[1][lane] + red[2][lane] + red[3][lane];
        g_tmp[nc * VV + lane] = tot * (1.0f / TT);
    }
}

// ---------------- weight split ----------------
// WHICH 0: pre, padded to MPAD rows (zeros beyond KM). WHICH 1: post.
template <int WHICH>
__global__ void wsplit_kernel(const float* __restrict__ src, int nelem, int srcrows, int cols) {
    int i = blockIdx.x * blockDim.x + threadIdx.x;
    if (i >= nelem) return;
    __nv_bfloat16* hi = WHICH == 0 ? g_wpre_hi : g_wpost_hi;
    __nv_bfloat16* lo = WHICH == 0 ? g_wpre_lo : g_wpost_lo;
    int row = i / cols;
    float v = (row < srcrows) ? src[i] : 0.f;
    __nv_bfloat16 h, l;
    split1(v, h, l);
    hi[i] = h;
    lo[i] = l;
}

// ---------------- bf16x3 MMA GEMM: CTA 128x128, warp tile 64x32 ----------------
// C[m][tv] = W[m][k] * B[k][tv]; NR = true output rows (store-guarded).
template <int KD, int NR, bool IS_POST>
__global__ __launch_bounds__(256) void gemm_mma(
    const __nv_bfloat16* __restrict__ Bhi, const __nv_bfloat16* __restrict__ Blo,
    const __nv_bfloat16* __restrict__ Whi, const __nv_bfloat16* __restrict__ Wlo,
    const float* __restrict__ bias, const float* __restrict__ gam,
    const float* __restrict__ bet,
    const float* __restrict__ resid, float* __restrict__ outp)
{
    __shared__ __align__(16) unsigned short As_h[128][40], As_l[128][40];   // 10240 B each
    __shared__ __align__(16) unsigned short Bs_h[32][136], Bs_l[32][136];   //  8704 B each

    const int tid  = threadIdx.x;
    const int lane = tid & 31;
    const int warp = tid >> 5;
    const int wm   = warp >> 2;   // 0..1  (m half: 64 rows)
    const int wn   = warp & 3;    // 0..3  (n quarter: 32 cols)
    const int n    = blockIdx.z;
    const int m0   = blockIdx.y * 128;
    const int c0   = blockIdx.x * 128;

    const __nv_bfloat16* Bhn = Bhi + (size_t)n * KD * TV;
    const __nv_bfloat16* Bln = Blo + (size_t)n * KD * TV;

    // staging map: A 128x32 halves -> thread: row=tid>>1, 16 halves at (tid&1)*16
    //              B  32x128 halves -> thread: row=tid>>3, 16 halves at (tid&7)*16
    const int arow = tid >> 1;
    const int acol = (tid & 1) * 16;
    const int brow = tid >> 3;
    const int bcol = (tid & 7) * 16;

    uint4 gA[4], gB[4];   // [hi0, hi1, lo0, lo1]
    {
        size_t ao = (size_t)(m0 + arow) * KD + acol;
        gA[0] = *(const uint4*)&Whi[ao];
        gA[1] = *(const uint4*)&Whi[ao + 8];
        gA[2] = *(const uint4*)&Wlo[ao];
        gA[3] = *(const uint4*)&Wlo[ao + 8];
        size_t bo = (size_t)brow * TV + c0 + bcol;
        gB[0] = *(const uint4*)&Bhn[bo];
        gB[1] = *(const uint4*)&Bhn[bo + 8];
        gB[2] = *(const uint4*)&Bln[bo];
        gB[3] = *(const uint4*)&Bln[bo + 8];
    }

    float acc[4][4][4];
    #pragma unroll
    for (int mi = 0; mi < 4; mi++)
        #pragma unroll
        for (int ni = 0; ni < 4; ni++)
            #pragma unroll
            for (int j = 0; j < 4; j++) acc[mi][ni][j] = 0.f;

    const uint32_t ash = smem_u32(As_h), asl = smem_u32(As_l);
    const uint32_t bsh = smem_u32(Bs_h), bsl = smem_u32(Bs_l);

    const int a_row = (lane & 7) + ((lane >> 3) & 1) * 8;
    const int a_kof = (lane >> 4) * 8;
    const int b_kof = (lane & 7) + ((lane >> 3) & 1) * 8;
    const int b_nof = wn * 32 + (lane >> 4) * 8;

    for (int k0 = 0; k0 < KD; k0 += 32) {
        *(uint4*)&As_h[arow][acol]     = gA[0];
        *(uint4*)&As_h[arow][acol + 8] = gA[1];
        *(uint4*)&As_l[arow][acol]     = gA[2];
        *(uint4*)&As_l[arow][acol + 8] = gA[3];
        *(uint4*)&Bs_h[brow][bcol]     = gB[0];
        *(uint4*)&Bs_h[brow][bcol + 8] = gB[1];
        *(uint4*)&Bs_l[brow][bcol]     = gB[2];
        *(uint4*)&Bs_l[brow][bcol + 8] = gB[3];
        __syncthreads();

        if (k0 + 32 < KD) {
            size_t ao = (size_t)(m0 + arow) * KD + k0 + 32 + acol;
            gA[0] = *(const uint4*)&Whi[ao];
            gA[1] = *(const uint4*)&Whi[ao + 8];
            gA[2] = *(const uint4*)&Wlo[ao];
            gA[3] = *(const uint4*)&Wlo[ao + 8];
            size_t bo = (size_t)(k0 + 32 + brow) * TV + c0 + bcol;
            gB[0] = *(const uint4*)&Bhn[bo];
            gB[1] = *(const uint4*)&Bhn[bo + 8];
            gB[2] = *(const uint4*)&Bln[bo];
            gB[3] = *(const uint4*)&Bln[bo + 8];
        }

        #pragma unroll
        for (int kk = 0; kk < 32; kk += 16) {
            uint32_t ah[4][4], al2[4][4], bh[4][2], bl[4][2];
            #pragma unroll
            for (int mi = 0; mi < 4; mi++) {
                uint32_t off = (uint32_t)((wm * 64 + mi * 16 + a_row) * 40 + kk + a_kof) * 2;
                ldsm4(ah[mi],  ash + off);
                ldsm4(al2[mi], asl + off);
            }
            #pragma unroll
            for (int p = 0; p < 2; p++) {
                uint32_t off = (uint32_t)((kk + b_kof) * 136 + b_nof + p * 16) * 2;
                uint32_t r[4];
                ldsm4t(r, bsh + off);
                bh[p * 2][0] = r[0]; bh[p * 2][1] = r[1];
                bh[p * 2 + 1][0] = r[2]; bh[p * 2 + 1][1] = r[3];
                ldsm4t(r, bsl + off);
                bl[p * 2][0] = r[0]; bl[p * 2][1] = r[1];
                bl[p * 2 + 1][0] = r[2]; bl[p * 2 + 1][1] = r[3];
            }
            #pragma unroll
            for (int mi = 0; mi < 4; mi++)
                #pragma unroll
                for (int ni = 0; ni < 4; ni++) {
                    mma_bf16(acc[mi][ni], ah[mi],  bh[ni]);
                    mma_bf16(acc[mi][ni], ah[mi],  bl[ni]);
                    mma_bf16(acc[mi][ni], al2[mi], bh[ni]);
                }
        }
        __syncthreads();
    }

    const float rs = rsqrtf(1.f + 1e-5f);
    float* outbase = IS_POST ? outp : (float*)g_prex;
    #pragma unroll
    for (int mi = 0; mi < 4; mi++) {
        int mb = m0 + wm * 64 + mi * 16 + (lane >> 2);
        #pragma unroll
        for (int rr = 0; rr < 2; rr++) {
            int m = mb + rr * 8;
            if (m < NR) {   // warp-uniform guard (pre-GEMM padding rows)
                float sc = gam[m] * rs, b1 = bias[m], b2 = bet[m];
                float* dst = outbase + ((size_t)n * NR + m) * TV + c0;
                const float* rsd = IS_POST ? resid + ((size_t)n * NR + m) * TV + c0 : nullptr;
                #pragma unroll
                for (int ni = 0; ni < 4; ni++) {
                    int col = wn * 32 + ni * 8 + (lane & 3) * 2;
                    float v0 = (acc[mi][ni][rr * 2 + 0] + b1) * sc + b2;
                    float v1 = (acc[mi][ni][rr * 2 + 1] + b1) * sc + b2;
                    if (IS_POST) { v0 += rsd[col]; v1 += rsd[col + 1]; }
                    float2 o = make_float2(fmaxf(v0, 0.f), fmaxf(v1, 0.f));
                    *(float2*)&dst[col] = o;
                }
            }
        }
    }
}

// ---------------- attention part 1: x1/x2 projection ----------------
#define COG 16
__global__ __launch_bounds__(256) void attn_x12_kernel(
    const float* __restrict__ c1w, const float* __restrict__ c1b,
    const float* __restrict__ c2w, const float* __restrict__ c2b)
{
    const int cg  = blockIdx.x;
    const int n   = blockIdx.y;
    const int tid = threadIdx.x;
    const int co0 = cg * COG;

    __shared__ float tmp_s[CC * VV];
    __shared__ float w1s[COG * CC];
    __shared__ float w2s[COG * CC];

    const float* tsrc = g_tmp + (size_t)n * CC * VV;
    for (int i = tid; i < CC * VV; i += 256) tmp_s[i] = tsrc[i];
    for (int i = tid; i < COG * CC; i += 256) {
        int r = i / CC, c = i % CC;
        w1s[i] = c1w[(size_t)(co0 + r) * CC + c];
        w2s[i] = c2w[(size_t)(co0 + r) * CC + c];
    }
    __syncthreads();

    #pragma unroll
    for (int base = 0; base < 512; base += 256) {
        int task = base + tid;
        if (task < COG * VV) {
            int co = task / VV, a = task % VV;
            float a1 = c1b[co0 + co], a2 = c2b[co0 + co];
            const float* w1 = &w1s[co * CC];
            const float* w2 = &w2s[co * CC];
            #pragma unroll 8
            for (int c = 0; c < CC; c++) {
                float tv = tmp_s[c * VV + a];
                a1 = fmaf(w1[c], tv, a1);
                a2 = fmaf(w2[c], tv, a2);
            }
            size_t o = (size_t)n * KM * VV + (size_t)(co0 + co) * VV + a;
            g_x1[o] = a1;
            g_x2[o] = a2;
        }
    }
}

// ---------------- attention part 2: g = x1.x2, softmax, beta ----------------
__global__ __launch_bounds__(256) void attn_g_kernel(const float* __restrict__ beta) {
    int nk  = blockIdx.x;
    int k   = nk % KK;
    int tid = threadIdx.x;

    __shared__ float x1_s[MIDC * VV];
    __shared__ float x2_s[MIDC * VV];
    __shared__ float g_s[VV * VV];

    const float* x1g = g_x1 + (size_t)nk * MIDC * VV;
    const float* x2g = g_x2 + (size_t)nk * MIDC * VV;
    for (int i = tid; i < MIDC * VV; i += 256) { x1_s[i] = x1g[i]; x2_s[i] = x2g[i]; }
    __syncthreads();

    for (int i = tid; i < VV * VV; i += 256) {
        int a = i / VV, b = i % VV;
        float acc = 0.f;
        #pragma unroll 8
        for (int c = 0; c < MIDC; c++)
            acc = fmaf(x1_s[c * VV + a], x2_s[c * VV + b], acc);
        g_s[i] = acc;
    }
    __syncthreads();

    if (tid < VV) {
        int b = tid;
        float m = -1e30f;
        for (int a = 0; a < VV; a++) m = fmaxf(m, g_s[a * VV + b]);
        float ssum = 0.f;
        float e[VV];
        for (int a = 0; a < VV; a++) { e[a] = expf(g_s[a * VV + b] - m); ssum += e[a]; }
        float sc = beta[k] / ssum;
        for (int a = 0; a < VV; a++) g_s[a * VV + b] = e[a] * sc;
    }
    __syncthreads();

    float* gso = g_gs + (size_t)nk * VV * VV;
    for (int i = tid; i < VV * VV; i += 256) gso[i] = g_s[i];
}

// ---------------- kernel 4: fused Afull + graph aggregation ----------------
__global__ __launch_bounds__(128) void agg_kernel(
    const float* __restrict__ A, const float* __restrict__ alpha)
{
    int idx = blockIdx.x;
    int tid = threadIdx.x;
    int n   = idx / KM;
    int kmr = idx % KM;
    int k   = kmr / MIDC;
    int nk  = n * KK + k;

    __shared__ __align__(16) float Af[VV * VV];
    __shared__ __align__(16) float px[TT * VV];
    __shared__ __align__(16) float ys[TT * VV];
    __shared__ float x1s[VV], x2s[VV];

    if (tid < VV) {
        x1s[tid] = g_x1[(size_t)n * KM * VV + (size_t)kmr * VV + tid];
        x2s[tid] = g_x2[(size_t)n * KM * VV + (size_t)kmr * VV + tid];
    }
    const float* pxg = g_prex + (size_t)idx * TV;
    for (int i = tid; i < TV; i += 128) px[i] = pxg[i];
    __syncthreads();

    float al = alpha[k];
    const float* Ak  = A + k * VV * VV;
    const float* gsk = g_gs + (size_t)nk * VV * VV;
    for (int i = tid; i < VV * VV; i += 128) {
        int u = i / VV, v = i % VV;
        Af[i] = tanhf(x1s[u] - x2s[v]) * al + Ak[i] + gsk[i];
    }
    __syncthreads();

    int t = tid;
    float pr[VV];
    #pragma unroll
    for (int v = 0; v < VV; v++) pr[v] = px[t * VV + v];
    #pragma unroll
    for (int u = 0; u < VV; u++) {
        float accv = 0.f;
        #pragma unroll
        for (int v = 0; v < VV; v++)
            accv = fmaf(pr[v], Af[u * VV + v], accv);
        ys[t * VV + u] = accv;
    }
    __syncthreads();

    size_t ob = (size_t)idx * TV;
    uint32_t* yh = (uint32_t*)(g_y_hi + ob);
    uint32_t* yl = (uint32_t*)(g_y_lo + ob);
    const float2* y2 = (const float2*)ys;
    for (int i = tid; i < TV / 2; i += 128) {
        float2 v = y2[i];
        uint32_t h, l;
        split2pk(v.x, v.y, h, l);
        yh[i] = h;
        yl[i] = l;
    }
}

// ---------------- launch ----------------
extern "C" void kernel_launch(void* const* d_in, const int* in_sizes, int n_in,
                              void* d_out, int out_size)
{
    const float* x       = (const float*)d_in[0];
    const float* A       = (const float*)d_in[1];
    const float* alpha   = (const float*)d_in[2];
    const float* beta    = (const float*)d_in[3];
    const float* pre_w   = (const float*)d_in[4];
    const float* pre_b   = (const float*)d_in[5];
    const float* pre_g   = (const float*)d_in[6];
    const float* pre_be  = (const float*)d_in[7];
    const float* conv1_w = (const float*)d_in[8];
    const float* conv1_b = (const float*)d_in[9];
    const float* conv2_w = (const float*)d_in[10];
    const float* conv2_b = (const float*)d_in[11];
    const float* post_w  = (const float*)d_in[12];
    const float* post_b  = (const float*)d_in[13];
    const float* bn_g    = (const float*)d_in[14];
    const float* bn_b    = (const float*)d_in[15];
    float* out = (float*)d_out;

    __nv_bfloat16 *xh, *xl, *yh, *yl, *wph, *wpl, *woh, *wol;
    cudaGetSymbolAddress((void**)&xh,  g_x_hi);
    cudaGetSymbolAddress((void**)&xl,  g_x_lo);
    cudaGetSymbolAddress((void**)&yh,  g_y_hi);
    cudaGetSymbolAddress((void**)&yl,  g_y_lo);
    cudaGetSymbolAddress((void**)&wph, g_wpre_hi);
    cudaGetSymbolAddress((void**)&wpl, g_wpre_lo);
    cudaGetSymbolAddress((void**)&woh, g_wpost_hi);
    cudaGetSymbolAddress((void**)&wol, g_wpost_lo);

    // launch order: gemm_pre is the 4th launch (ncu profile window)
    mean_split_kernel<<<NN * CC, 128>>>(x);
    wsplit_kernel<0><<<(MPAD * CC + 255) / 256, 256>>>(pre_w, MPAD * CC, KM, CC);
    wsplit_kernel<1><<<(OUTC * KM + 255) / 256, 256>>>(post_w, OUTC * KM, OUTC, KM);

    gemm_mma<CC, KM, false><<<dim3(TV / 128, MPAD / 128, NN), 256>>>(
        xh, xl, wph, wpl, pre_b, pre_g, pre_be, nullptr, nullptr);

    attn_x12_kernel<<<dim3(KM / COG, NN), 256>>>(conv1_w, conv1_b, conv2_w, conv2_b);
    attn_g_kernel<<<NN * KK, 256>>>(beta);

    agg_kernel<<<NN * KM, 128>>>(A, alpha);

    gemm_mma<KM, OUTC, true><<<dim3(TV / 128, OUTC / 128, NN), 256>>>(
        yh, yl, woh, wol, post_b, bn_g, bn_b, x, out);
}

// round 10
// speedup vs baseline: 1.2813x; 1.2813x over previous
#include <cuda_runtime.h>
#include <cuda_bf16.h>
#include <cstdint>

#define NN   32
#define CC   256
#define TT   128
#define VV   25
#define KK   3
#define MIDC 64
#define KM   192
#define OUTC 256
#define TV   3200
#define MPAD 256    // padded M for pre-GEMM weights

// ---------------- scratch (device globals; no allocation) ----------------
__device__ __align__(256) float g_tmp[NN * CC * VV];
__device__ __align__(256) float g_x1[NN * KK * MIDC * VV];
__device__ __align__(256) float g_x2[NN * KK * MIDC * VV];
__device__ __align__(256) float g_gs[NN * KK * VV * VV];
__device__ __align__(256) float g_prex[NN * KM * TV];
__device__ __align__(256) __nv_bfloat16 g_x_hi[(size_t)NN * CC * TV];
__device__ __align__(256) __nv_bfloat16 g_x_lo[(size_t)NN * CC * TV];
__device__ __align__(256) __nv_bfloat16 g_y_hi[(size_t)NN * KM * TV];
__device__ __align__(256) __nv_bfloat16 g_y_lo[(size_t)NN * KM * TV];
__device__ __align__(256) __nv_bfloat16 g_wpre_hi[MPAD * CC];   // rows >= KM are zero
__device__ __align__(256) __nv_bfloat16 g_wpre_lo[MPAD * CC];
__device__ __align__(256) __nv_bfloat16 g_wpost_hi[OUTC * KM];
__device__ __align__(256) __nv_bfloat16 g_wpost_lo[OUTC * KM];

// ---------------- helpers ----------------
__device__ __forceinline__ uint32_t smem_u32(const void* p) {
    uint32_t a;
    asm("{ .reg .u64 t; cvta.to.shared.u64 t, %1; cvt.u32.u64 %0, t; }" : "=r"(a) : "l"(p));
    return a;
}
__device__ __forceinline__ void ldsm4(uint32_t* r, uint32_t addr) {
    asm volatile("ldmatrix.sync.aligned.m8n8.x4.shared.b16 {%0,%1,%2,%3}, [%4];"
                 : "=r"(r[0]), "=r"(r[1]), "=r"(r[2]), "=r"(r[3]) : "r"(addr));
}
__device__ __forceinline__ void ldsm4t(uint32_t* r, uint32_t addr) {
    asm volatile("ldmatrix.sync.aligned.m8n8.x4.trans.shared.b16 {%0,%1,%2,%3}, [%4];"
                 : "=r"(r[0]), "=r"(r[1]), "=r"(r[2]), "=r"(r[3]) : "r"(addr));
}
__device__ __forceinline__ void mma_bf16(float* d, const uint32_t* a, const uint32_t* b) {
    asm volatile(
        "mma.sync.aligned.m16n8k16.row.col.f32.bf16.bf16.f32 "
        "{%0,%1,%2,%3}, {%4,%5,%6,%7}, {%8,%9}, {%0,%1,%2,%3};"
        : "+f"(d[0]), "+f"(d[1]), "+f"(d[2]), "+f"(d[3])
        : "r"(a[0]), "r"(a[1]), "r"(a[2]), "r"(a[3]), "r"(b[0]), "r"(b[1]));
}
__device__ __forceinline__ void cpa16(uint32_t dst, const void* src) {
    asm volatile("cp.async.cg.shared.global [%0], [%1], 16;" :: "r"(dst), "l"(src));
}
#define CP_COMMIT() asm volatile("cp.async.commit_group;" ::: "memory")
#define CP_WAIT1()  asm volatile("cp.async.wait_group 1;" ::: "memory")
__device__ __forceinline__ uint32_t pack_bf(__nv_bfloat16 a, __nv_bfloat16 b) {
    return ((uint32_t)__bfloat16_as_ushort(b) << 16) | (uint32_t)__bfloat16_as_ushort(a);
}
__device__ __forceinline__ void split2pk(float x, float y, uint32_t& hi, uint32_t& lo) {
    __nv_bfloat16 hx = __float2bfloat16(x);
    __nv_bfloat16 hy = __float2bfloat16(y);
    hi = pack_bf(hx, hy);
    lo = pack_bf(__float2bfloat16(x - __bfloat162float(hx)),
                 __float2bfloat16(y - __bfloat162float(hy)));
}
__device__ __forceinline__ void split1(float v, __nv_bfloat16& h, __nv_bfloat16& l) {
    h = __float2bfloat16(v);
    l = __float2bfloat16(v - __bfloat162float(h));
}

// ---------------- kernel 1: mean over T + x bf16 split ----------------
__global__ void mean_split_kernel(const float* __restrict__ x) {
    int nc   = blockIdx.x;
    int tid  = threadIdx.x;
    int lane = tid & 31;
    int warp = tid >> 5;
    const float* base = x + (size_t)nc * (TT * VV);

    const float2* b2 = (const float2*)base;
    uint32_t* xh = (uint32_t*)(g_x_hi + (size_t)nc * (TT * VV));
    uint32_t* xl = (uint32_t*)(g_x_lo + (size_t)nc * (TT * VV));
    for (int i = tid; i < (TT * VV) / 2; i += 128) {
        float2 v = b2[i];
        uint32_t h, l;
        split2pk(v.x, v.y, h, l);
        xh[i] = h;
        xl[i] = l;
    }

    __shared__ float red[4][VV];
    if (lane < VV) {
        float s = 0.f;
        for (int t = warp; t < TT; t += 4)
            s += base[t * VV + lane];
        red[warp][lane] = s;
    }
    __syncthreads();
    if (warp == 0 && lane < VV) {
        float tot = red[0][lane] + red[1][lane] + red[2][lane] + red[3][lane];
        g_tmp[nc * VV + lane] = tot * (1.0f / TT);
    }
}

// ---------------- weight split ----------------
template <int WHICH>
__global__ void wsplit_kernel(const float* __restrict__ src, int nelem, int srcrows, int cols) {
    int i = blockIdx.x * blockDim.x + threadIdx.x;
    if (i >= nelem) return;
    __nv_bfloat16* hi = WHICH == 0 ? g_wpre_hi : g_wpost_hi;
    __nv_bfloat16* lo = WHICH == 0 ? g_wpre_lo : g_wpost_lo;
    int row = i / cols;
    float v = (row < srcrows) ? src[i] : 0.f;
    __nv_bfloat16 h, l;
    split1(v, h, l);
    hi[i] = h;
    lo[i] = l;
}

// ---------------- bf16x3 MMA GEMM: CTA 128x128, BK=16, 2-stage cp.async ----------------
// warp tile 64x32 (8 warps: 2 m-halves x 4 n-quarters). NR = true output rows.
template <int KD, int NR, bool IS_POST>
__global__ __launch_bounds__(256, 2) void gemm_mma(
    const __nv_bfloat16* __restrict__ Bhi, const __nv_bfloat16* __restrict__ Blo,
    const __nv_bfloat16* __restrict__ Whi, const __nv_bfloat16* __restrict__ Wlo,
    const float* __restrict__ bias, const float* __restrict__ gam,
    const float* __restrict__ bet,
    const float* __restrict__ resid, float* __restrict__ outp)
{
    // 2 stages: A 2*128*24*2B *2(hi,lo) = 24576 B, B 2*16*136*2B *2 = 17408 B -> 41984 B
    __shared__ __align__(16) unsigned short As_h[2][128][24], As_l[2][128][24];
    __shared__ __align__(16) unsigned short Bs_h[2][16][136], Bs_l[2][16][136];

    const int tid  = threadIdx.x;
    const int lane = tid & 31;
    const int warp = tid >> 5;
    const int wm   = warp >> 2;   // m half (64 rows)
    const int wn   = warp & 3;    // n quarter (32 cols)
    const int n    = blockIdx.z;
    const int m0   = blockIdx.y * 128;
    const int c0   = blockIdx.x * 128;

    const __nv_bfloat16* Bhn = Bhi + (size_t)n * KD * TV;
    const __nv_bfloat16* Bln = Blo + (size_t)n * KD * TV;

    // cp.async maps: A stage 128x16 halves -> 1 chunk/thread (arow=tid>>1, acol=(tid&1)*8)
    //                B stage  16x128 halves -> 1 chunk/thread (brow=tid>>4, bcol=(tid&15)*8)
    const int arow = tid >> 1;
    const int acol = (tid & 1) * 8;
    const int brow = tid >> 4;
    const int bcol = (tid & 15) * 8;

    const uint32_t ash0 = smem_u32(&As_h[0][arow][acol]);
    const uint32_t asl0 = smem_u32(&As_l[0][arow][acol]);
    const uint32_t bsh0 = smem_u32(&Bs_h[0][brow][bcol]);
    const uint32_t bsl0 = smem_u32(&Bs_l[0][brow][bcol]);
    const uint32_t ABUF = 128 * 24 * 2;   // bytes per A stage
    const uint32_t BBUF = 16 * 136 * 2;   // bytes per B stage

    const __nv_bfloat16* aph = Whi + (size_t)(m0 + arow) * KD + acol;
    const __nv_bfloat16* apl = Wlo + (size_t)(m0 + arow) * KD + acol;
    const __nv_bfloat16* bph = Bhn + (size_t)brow * TV + c0 + bcol;
    const __nv_bfloat16* bpl = Bln + (size_t)brow * TV + c0 + bcol;

    float acc[4][4][4];
    #pragma unroll
    for (int mi = 0; mi < 4; mi++)
        #pragma unroll
        for (int ni = 0; ni < 4; ni++)
            #pragma unroll
            for (int j = 0; j < 4; j++) acc[mi][ni][j] = 0.f;

    const uint32_t ashb = smem_u32(As_h);
    const uint32_t aslb = smem_u32(As_l);
    const uint32_t bshb = smem_u32(Bs_h);
    const uint32_t bslb = smem_u32(Bs_l);

    const int a_row = (lane & 7) + ((lane >> 3) & 1) * 8;
    const int a_kof = (lane >> 4) * 8;
    const int b_kof = (lane & 7) + ((lane >> 3) & 1) * 8;
    const int b_nof = wn * 32 + (lane >> 4) * 8;

    const int NSTAGE = KD / 16;

    // prologue: stage 0 -> buf 0
    cpa16(ash0, aph);
    cpa16(asl0, apl);
    cpa16(bsh0, bph);
    cpa16(bsl0, bpl);
    CP_COMMIT();

    for (int s = 0; s < NSTAGE; s++) {
        const int buf = s & 1;
        if (s + 1 < NSTAGE) {
            const int nb = buf ^ 1;
            cpa16(ash0 + nb * ABUF, aph + (s + 1) * 16);
            cpa16(asl0 + nb * ABUF, apl + (s + 1) * 16);
            cpa16(bsh0 + nb * BBUF, bph + (size_t)(s + 1) * 16 * TV);
            cpa16(bsl0 + nb * BBUF, bpl + (size_t)(s + 1) * 16 * TV);
        }
        CP_COMMIT();
        CP_WAIT1();          // stage s resident (only stage s+1 may be in flight)
        __syncthreads();

        uint32_t ah[4][4], al2[4][4], bh[4][2], bl[4][2];
        #pragma unroll
        for (int mi = 0; mi < 4; mi++) {
            uint32_t off = buf * ABUF + (uint32_t)((wm * 64 + mi * 16 + a_row) * 24 + a_kof) * 2;
            ldsm4(ah[mi],  ashb + off);
            ldsm4(al2[mi], aslb + off);
        }
        #pragma unroll
        for (int p = 0; p < 2; p++) {
            uint32_t off = buf * BBUF + (uint32_t)(b_kof * 136 + b_nof + p * 16) * 2;
            uint32_t r[4];
            ldsm4t(r, bshb + off);
            bh[p * 2][0] = r[0]; bh[p * 2][1] = r[1];
            bh[p * 2 + 1][0] = r[2]; bh[p * 2 + 1][1] = r[3];
            ldsm4t(r, bslb + off);
            bl[p * 2][0] = r[0]; bl[p * 2][1] = r[1];
            bl[p * 2 + 1][0] = r[2]; bl[p * 2 + 1][1] = r[3];
        }
        #pragma unroll
        for (int mi = 0; mi < 4; mi++)
            #pragma unroll
            for (int ni = 0; ni < 4; ni++) {
                mma_bf16(acc[mi][ni], ah[mi],  bh[ni]);
                mma_bf16(acc[mi][ni], ah[mi],  bl[ni]);
                mma_bf16(acc[mi][ni], al2[mi], bh[ni]);
            }
        __syncthreads();     // release buf before iter s+1 overwrites it
    }

    const float rs = rsqrtf(1.f + 1e-5f);
    float* outbase = IS_POST ? outp : (float*)g_prex;
    #pragma unroll
    for (int mi = 0; mi < 4; mi++) {
        int mb = m0 + wm * 64 + mi * 16 + (lane >> 2);
        #pragma unroll
        for (int rr = 0; rr < 2; rr++) {
            int m = mb + rr * 8;
            if (m < NR) {
                float sc = gam[m] * rs, b1 = bias[m], b2 = bet[m];
                float* dst = outbase + ((size_t)n * NR + m) * TV + c0;
                const float* rsd = IS_POST ? resid + ((size_t)n * NR + m) * TV + c0 : nullptr;
                #pragma unroll
                for (int ni = 0; ni < 4; ni++) {
                    int col = wn * 32 + ni * 8 + (lane & 3) * 2;
                    float v0 = (acc[mi][ni][rr * 2 + 0] + b1) * sc + b2;
                    float v1 = (acc[mi][ni][rr * 2 + 1] + b1) * sc + b2;
                    if (IS_POST) { v0 += rsd[col]; v1 += rsd[col + 1]; }
                    float2 o = make_float2(fmaxf(v0, 0.f), fmaxf(v1, 0.f));
                    *(float2*)&dst[col] = o;
                }
            }
        }
    }
}

// ---------------- attention part 1: x1/x2 projection ----------------
#define COG 16
__global__ __launch_bounds__(256) void attn_x12_kernel(
    const float* __restrict__ c1w, const float* __restrict__ c1b,
    const float* __restrict__ c2w, const float* __restrict__ c2b)
{
    const int cg  = blockIdx.x;
    const int n   = blockIdx.y;
    const int tid = threadIdx.x;
    const int co0 = cg * COG;

    __shared__ float tmp_s[CC * VV];
    __shared__ float w1s[COG * CC];
    __shared__ float w2s[COG * CC];

    const float* tsrc = g_tmp + (size_t)n * CC * VV;
    for (int i = tid; i < CC * VV; i += 256) tmp_s[i] = tsrc[i];
    for (int i = tid; i < COG * CC; i += 256) {
        int r = i / CC, c = i % CC;
        w1s[i] = c1w[(size_t)(co0 + r) * CC + c];
        w2s[i] = c2w[(size_t)(co0 + r) * CC + c];
    }
    __syncthreads();

    #pragma unroll
    for (int base = 0; base < 512; base += 256) {
        int task = base + tid;
        if (task < COG * VV) {
            int co = task / VV, a = task % VV;
            float a1 = c1b[co0 + co], a2 = c2b[co0 + co];
            const float* w1 = &w1s[co * CC];
            const float* w2 = &w2s[co * CC];
            #pragma unroll 8
            for (int c = 0; c < CC; c++) {
                float tv = tmp_s[c * VV + a];
                a1 = fmaf(w1[c], tv, a1);
                a2 = fmaf(w2[c], tv, a2);
            }
            size_t o = (size_t)n * KM * VV + (size_t)(co0 + co) * VV + a;
            g_x1[o] = a1;
            g_x2[o] = a2;
        }
    }
}

// ---------------- attention part 2: g = x1.x2, softmax, beta ----------------
__global__ __launch_bounds__(256) void attn_g_kernel(const float* __restrict__ beta) {
    int nk  = blockIdx.x;
    int k   = nk % KK;
    int tid = threadIdx.x;

    __shared__ float x1_s[MIDC * VV];
    __shared__ float x2_s[MIDC * VV];
    __shared__ float g_s[VV * VV];

    const float* x1g = g_x1 + (size_t)nk * MIDC * VV;
    const float* x2g = g_x2 + (size_t)nk * MIDC * VV;
    for (int i = tid; i < MIDC * VV; i += 256) { x1_s[i] = x1g[i]; x2_s[i] = x2g[i]; }
    __syncthreads();

    for (int i = tid; i < VV * VV; i += 256) {
        int a = i / VV, b = i % VV;
        float acc = 0.f;
        #pragma unroll 8
        for (int c = 0; c < MIDC; c++)
            acc = fmaf(x1_s[c * VV + a], x2_s[c * VV + b], acc);
        g_s[i] = acc;
    }
    __syncthreads();

    if (tid < VV) {
        int b = tid;
        float m = -1e30f;
        for (int a = 0; a < VV; a++) m = fmaxf(m, g_s[a * VV + b]);
        float ssum = 0.f;
        float e[VV];
        for (int a = 0; a < VV; a++) { e[a] = expf(g_s[a * VV + b] - m); ssum += e[a]; }
        float sc = beta[k] / ssum;
        for (int a = 0; a < VV; a++) g_s[a * VV + b] = e[a] * sc;
    }
    __syncthreads();

    float* gso = g_gs + (size_t)nk * VV * VV;
    for (int i = tid; i < VV * VV; i += 256) gso[i] = g_s[i];
}

// ---------------- kernel 4: fused Afull + graph aggregation ----------------
__global__ __launch_bounds__(128) void agg_kernel(
    const float* __restrict__ A, const float* __restrict__ alpha)
{
    int idx = blockIdx.x;
    int tid = threadIdx.x;
    int n   = idx / KM;
    int kmr = idx % KM;
    int k   = kmr / MIDC;
    int nk  = n * KK + k;

    __shared__ __align__(16) float Af[VV * VV];
    __shared__ __align__(16) float px[TT * VV];
    __shared__ __align__(16) float ys[TT * VV];
    __shared__ float x1s[VV], x2s[VV];

    if (tid < VV) {
        x1s[tid] = g_x1[(size_t)n * KM * VV + (size_t)kmr * VV + tid];
        x2s[tid] = g_x2[(size_t)n * KM * VV + (size_t)kmr * VV + tid];
    }
    const float* pxg = g_prex + (size_t)idx * TV;
    for (int i = tid; i < TV; i += 128) px[i] = pxg[i];
    __syncthreads();

    float al = alpha[k];
    const float* Ak  = A + k * VV * VV;
    const float* gsk = g_gs + (size_t)nk * VV * VV;
    for (int i = tid; i < VV * VV; i += 128) {
        int u = i / VV, v = i % VV;
        Af[i] = tanhf(x1s[u] - x2s[v]) * al + Ak[i] + gsk[i];
    }
    __syncthreads();

    int t = tid;
    float pr[VV];
    #pragma unroll
    for (int v = 0; v < VV; v++) pr[v] = px[t * VV + v];
    #pragma unroll
    for (int u = 0; u < VV; u++) {
        float accv = 0.f;
        #pragma unroll
        for (int v = 0; v < VV; v++)
            accv = fmaf(pr[v], Af[u * VV + v], accv);
        ys[t * VV + u] = accv;
    }
    __syncthreads();

    size_t ob = (size_t)idx * TV;
    uint32_t* yh = (uint32_t*)(g_y_hi + ob);
    uint32_t* yl = (uint32_t*)(g_y_lo + ob);
    const float2* y2 = (const float2*)ys;
    for (int i = tid; i < TV / 2; i += 128) {
        float2 v = y2[i];
        uint32_t h, l;
        split2pk(v.x, v.y, h, l);
        yh[i] = h;
        yl[i] = l;
    }
}

// ---------------- launch ----------------
extern "C" void kernel_launch(void* const* d_in, const int* in_sizes, int n_in,
                              void* d_out, int out_size)
{
    const float* x       = (const float*)d_in[0];
    const float* A       = (const float*)d_in[1];
    const float* alpha   = (const float*)d_in[2];
    const float* beta    = (const float*)d_in[3];
    const float* pre_w   = (const float*)d_in[4];
    const float* pre_b   = (const float*)d_in[5];
    const float* pre_g   = (const float*)d_in[6];
    const float* pre_be  = (const float*)d_in[7];
    const float* conv1_w = (const float*)d_in[8];
    const float* conv1_b = (const float*)d_in[9];
    const float* conv2_w = (const float*)d_in[10];
    const float* conv2_b = (const float*)d_in[11];
    const float* post_w  = (const float*)d_in[12];
    const float* post_b  = (const float*)d_in[13];
    const float* bn_g    = (const float*)d_in[14];
    const float* bn_b    = (const float*)d_in[15];
    float* out = (float*)d_out;

    __nv_bfloat16 *xh, *xl, *yh, *yl, *wph, *wpl, *woh, *wol;
    cudaGetSymbolAddress((void**)&xh,  g_x_hi);
    cudaGetSymbolAddress((void**)&xl,  g_x_lo);
    cudaGetSymbolAddress((void**)&yh,  g_y_hi);
    cudaGetSymbolAddress((void**)&yl,  g_y_lo);
    cudaGetSymbolAddress((void**)&wph, g_wpre_hi);
    cudaGetSymbolAddress((void**)&wpl, g_wpre_lo);
    cudaGetSymbolAddress((void**)&woh, g_wpost_hi);
    cudaGetSymbolAddress((void**)&wol, g_wpost_lo);

    // launch order: gemm_pre is the 4th launch (ncu profile window)
    mean_split_kernel<<<NN * CC, 128>>>(x);
    wsplit_kernel<0><<<(MPAD * CC + 255) / 256, 256>>>(pre_w, MPAD * CC, KM, CC);
    wsplit_kernel<1><<<(OUTC * KM + 255) / 256, 256>>>(post_w, OUTC * KM, OUTC, KM);

    gemm_mma<CC, KM, false><<<dim3(TV / 128, MPAD / 128, NN), 256>>>(
        xh, xl, wph, wpl, pre_b, pre_g, pre_be, nullptr, nullptr);

    attn_x12_kernel<<<dim3(KM / COG, NN), 256>>>(conv1_w, conv1_b, conv2_w, conv2_b);
    attn_g_kernel<<<NN * KK, 256>>>(beta);

    agg_kernel<<<NN * KM, 128>>>(A, alpha);

    gemm_mma<KM, OUTC, true><<<dim3(TV / 128, OUTC / 128, NN), 256>>>(
        yh, yl, woh, wol, post_b, bn_g, bn_b, x, out);
}